// round 2
// baseline (speedup 1.0000x reference)
#include <cuda_runtime.h>

// ---------------------------------------------------------------------------
// StableSpikingCoreFlow: T=64, B=128, D=N=2048, L=4, OUT=1024
//
// Identity: each layer only needs the TIME-AVERAGED input, because
//   mean_t( gathered_t @ W^T ) = ( mean_t gathered_t ) @ W^T
// and the next layer only consumes mean_t(spikes) = spike_count / T
// (rates c/64 are dyadic -> exact). Final output = spike counts at out_idx.
//
// Accuracy: chunked fp32 accumulation (32-k chunks) + Kahan compensated
// combine, so our avg is ~8x closer to the true dot than a single sequential
// accumulator; spike-count flips vs the reference drop proportionally.
// ---------------------------------------------------------------------------

#define Bc   128
#define Dc   2048
#define Nc   2048
#define Tc   64
#define Lc   4
#define OUTc 1024

#define BM 32
#define BN 64
#define BK 16
#define PAD 4
#define NTHREADS 128

// scratch (no cudaMalloc allowed)
__device__ float g_G [Bc * Dc];
__device__ float g_R0[Bc * Nc];
__device__ float g_R1[Bc * Nc];

// ---------------------------------------------------------------------------
__global__ void gather_kernel(const float* __restrict__ Rin,
                              const int*   __restrict__ axon,
                              float*       __restrict__ G)
{
    int idx = blockIdx.x * blockDim.x + threadIdx.x;
    if (idx >= Bc * Dc) return;
    int b = idx >> 11;
    int a = idx & 2047;
    G[idx] = Rin[(b << 11) + axon[a]];
}

// ---------------------------------------------------------------------------
__global__ __launch_bounds__(NTHREADS)
void layer_kernel(const float* __restrict__ G,     // [B, D]
                  const float* __restrict__ W,     // [N, D] row-major
                  const float* __restrict__ thresholds,
                  int l,
                  float* __restrict__ Rout)        // [B, N] rates = c/64
{
    __shared__ float As[BK][BM + PAD];
    __shared__ float Bs[BK][BN + PAD];

    const int bm = blockIdx.y * BM;   // over B
    const int bn = blockIdx.x * BN;   // over N

    const int tid  = threadIdx.x;
    const int warp = tid >> 5;
    const int lane = tid & 31;
    const int tm = (lane >> 2) * 4;            // [0,32) step 4
    const int tn = warp * 16 + (lane & 3) * 4; // [0,64) step 4

    float cacc[4][4];   // current chunk accumulator
    float ksum[4][4];   // Kahan sum
    float kcmp[4][4];   // Kahan compensation
#pragma unroll
    for (int i = 0; i < 4; i++)
#pragma unroll
        for (int j = 0; j < 4; j++) {
            cacc[i][j] = 0.f; ksum[i][j] = 0.f; kcmp[i][j] = 0.f;
        }

    int kblk = 0;
    for (int k0 = 0; k0 < Dc; k0 += BK, kblk++) {
        // A tile: 32 rows x 16 k  (128 float4 -> 1 per thread)
        {
            int m  = tid >> 2;
            int kv = (tid & 3) * 4;
            float4 v = *(const float4*)&G[(bm + m) * Dc + k0 + kv];
            As[kv + 0][m] = v.x; As[kv + 1][m] = v.y;
            As[kv + 2][m] = v.z; As[kv + 3][m] = v.w;
        }
        // B tile: 64 rows x 16 k  (256 float4 -> 2 per thread)
#pragma unroll
        for (int r = 0; r < 2; r++) {
            int i  = tid + r * NTHREADS;
            int n  = i >> 2;
            int kv = (i & 3) * 4;
            float4 v = *(const float4*)&W[(bn + n) * Dc + k0 + kv];
            Bs[kv + 0][n] = v.x; Bs[kv + 1][n] = v.y;
            Bs[kv + 2][n] = v.z; Bs[kv + 3][n] = v.w;
        }
        __syncthreads();

#pragma unroll
        for (int k = 0; k < BK; k++) {
            float4 a4 = *(const float4*)&As[k][tm];
            float4 b4 = *(const float4*)&Bs[k][tn];
            float a[4] = {a4.x, a4.y, a4.z, a4.w};
            float b[4] = {b4.x, b4.y, b4.z, b4.w};
#pragma unroll
            for (int i = 0; i < 4; i++)
#pragma unroll
                for (int j = 0; j < 4; j++)
                    cacc[i][j] = fmaf(a[i], b[j], cacc[i][j]);
        }
        __syncthreads();

        // Kahan fold every 2 BK blocks (chunk = 32 k values)
        if (kblk & 1) {
#pragma unroll
            for (int i = 0; i < 4; i++)
#pragma unroll
                for (int j = 0; j < 4; j++) {
                    float y = __fsub_rn(cacc[i][j], kcmp[i][j]);
                    float t = __fadd_rn(ksum[i][j], y);
                    kcmp[i][j] = __fsub_rn(__fsub_rn(t, ksum[i][j]), y);
                    ksum[i][j] = t;
                    cacc[i][j] = 0.f;
                }
        }
    }

    // fused spike scan: exact fp32 semantics of the reference
    //   m += avg; s = (m > thr); m -= thr*s; count += s   (T=64)
    const float thr = thresholds[l];
#pragma unroll
    for (int i = 0; i < 4; i++) {
#pragma unroll
        for (int j = 0; j < 4; j++) {
            float a = ksum[i][j];
            int c;
            if (a <= 0.f) {
                c = 0;                      // thr > 0, m never exceeds thr
            } else if (a > thr) {
                c = Tc;                     // spikes every step, exactly
            } else {
                float m = 0.f;
                c = 0;
                for (int t = 0; t < Tc; t++) {
                    m += a;
                    if (m > thr) { m -= thr; c++; }
                }
            }
            Rout[(bm + tm + i) * Nc + (bn + tn + j)] = (float)c * (1.0f / Tc);
        }
    }
}

// ---------------------------------------------------------------------------
__global__ void out_kernel(const float* __restrict__ R,
                           const int*   __restrict__ out_idx,
                           float*       __restrict__ out)
{
    int idx = blockIdx.x * blockDim.x + threadIdx.x;
    if (idx >= Bc * OUTc) return;
    int b = idx >> 10;
    int o = idx & 1023;
    out[idx] = R[(b << 11) + out_idx[o]] * (float)Tc;  // rate*64 = count, exact
}

// ---------------------------------------------------------------------------
extern "C" void kernel_launch(void* const* d_in, const int* in_sizes, int n_in,
                              void* d_out, int out_size)
{
    const float* x       = (const float*)d_in[0];   // [B, D]
    const float* W       = (const float*)d_in[1];   // [L, N, D]
    const float* thr     = (const float*)d_in[2];   // [L]
    const int*   axon    = (const int*)  d_in[3];   // [L, D]
    const int*   out_idx = (const int*)  d_in[4];   // [OUT]
    (void)in_sizes; (void)n_in; (void)out_size;

    float *G, *R0, *R1;
    cudaGetSymbolAddress((void**)&G,  g_G);
    cudaGetSymbolAddress((void**)&R0, g_R0);
    cudaGetSymbolAddress((void**)&R1, g_R1);
    float* bufs[2] = { R0, R1 };

    dim3 ggrid((Bc * Dc + 255) / 256);
    dim3 lgrid(Nc / BN, Bc / BM);   // (32, 4) = 128 blocks

    const float* rin = x;
    for (int l = 0; l < Lc; l++) {
        gather_kernel<<<ggrid, 256>>>(rin, axon + l * Dc, G);
        layer_kernel <<<lgrid, NTHREADS>>>(G, W + (size_t)l * Nc * Dc, thr, l,
                                           bufs[l & 1]);
        rin = bufs[l & 1];
    }
    out_kernel<<<(Bc * OUTc + 255) / 256, 256>>>(rin, out_idx, (float*)d_out);
}

// round 3
// speedup vs baseline: 2.0151x; 2.0151x over previous
#include <cuda_runtime.h>

// ---------------------------------------------------------------------------
// StableSpikingCoreFlow: T=64, B=128, D=N=2048, L=4, OUT=1024
//
// Identity: each layer only needs the TIME-AVERAGED input
//   mean_t( gathered_t @ W^T ) = ( mean_t gathered_t ) @ W^T,
// next layer consumes mean_t(spikes) = count/64 (dyadic -> exact).
// Final output = total spike counts gathered at out_idx.
//
// Round 3: in-block split-K x4 (512 threads, 16 warps/block -> 16 warps/SM)
// + software-pipelined tile loads. Per-group accumulation is identical to
// round 2 (fp32 FMA chains, Kahan fold every 32 k, chunk boundaries aligned
// with the k=512 group splits); group partials merged in fixed order.
// ---------------------------------------------------------------------------

#define Bc   128
#define Dc   2048
#define Nc   2048
#define Tc   64
#define Lc   4
#define OUTc 1024

#define BM 32
#define BN 64
#define BK 16
#define NTHREADS 512
#define NGROUPS 4
#define KSLICE (Dc / NGROUPS)   // 512
#define NKB (KSLICE / BK)       // 32

// smem layout (floats)
#define AROW 36                  // BM + 4 pad (144B rows, 16B-aligned)
#define BROW 68                  // BN + 4 pad (272B rows, 16B-aligned)
#define AS_SZ (BK * AROW)        // 576
#define BS_SZ (BK * BROW)        // 1088
#define TILE_SZ (AS_SZ + BS_SZ)  // 1664 per group
#define PS_OFF (NGROUPS * TILE_SZ)          // 6656
#define SMEM_FLOATS (PS_OFF + NGROUPS * BM * BN)   // 6656 + 8192 = 14848
#define SMEM_BYTES (SMEM_FLOATS * 4)               // 59392

// scratch (no cudaMalloc allowed)
__device__ float g_G [Bc * Dc];
__device__ float g_R0[Bc * Nc];
__device__ float g_R1[Bc * Nc];

// ---------------------------------------------------------------------------
__global__ void gather_kernel(const float* __restrict__ Rin,
                              const int*   __restrict__ axon,
                              float*       __restrict__ G)
{
    int idx = blockIdx.x * blockDim.x + threadIdx.x;
    if (idx >= Bc * Dc) return;
    int b = idx >> 11;
    int a = idx & 2047;
    G[idx] = Rin[(b << 11) + axon[a]];
}

// ---------------------------------------------------------------------------
__global__ __launch_bounds__(NTHREADS, 1)
void layer_kernel(const float* __restrict__ G,     // [B, D]
                  const float* __restrict__ W,     // [N, D] row-major
                  const float* __restrict__ thresholds,
                  int l,
                  float* __restrict__ Rout)        // [B, N] rates = c/64
{
    extern __shared__ float sm[];

    const int tid = threadIdx.x;
    const int gid = tid >> 7;      // k-split group 0..3
    const int gt  = tid & 127;     // thread within group

    float* As = sm + gid * TILE_SZ;            // [BK][AROW]
    float* Bs = sm + gid * TILE_SZ + AS_SZ;    // [BK][BROW]
    float* Ps = sm + PS_OFF;                   // [NGROUPS][BM*BN]

    const int bm = blockIdx.y * BM;   // over B
    const int bn = blockIdx.x * BN;   // over N
    const int kbase = gid * KSLICE;

    const int warp = gt >> 5;
    const int lane = gt & 31;
    const int tm = (lane >> 2) * 4;            // [0,32) step 4
    const int tn = warp * 16 + (lane & 3) * 4; // [0,64) step 4

    // tile-load indices
    const int am = gt >> 2;          // 0..31 (A row)
    const int ak = (gt & 3) * 4;     // k sub-offset for A
    const int n0 = gt >> 2;          // 0..31 (B row, r=0)
    const int n1 = (gt + 128) >> 2;  // 32..63 (B row, r=1)
    const int bk0 = (gt & 3) * 4;    // k sub-offset (same both rows)

    float cacc[4][4], ksum[4][4], kcmp[4][4];
#pragma unroll
    for (int i = 0; i < 4; i++)
#pragma unroll
        for (int j = 0; j < 4; j++) {
            cacc[i][j] = 0.f; ksum[i][j] = 0.f; kcmp[i][j] = 0.f;
        }

    // prefetch tile kb=0
    float4 pa  = *(const float4*)&G[(bm + am) * Dc + kbase + ak];
    float4 pb0 = *(const float4*)&W[(bn + n0) * Dc + kbase + bk0];
    float4 pb1 = *(const float4*)&W[(bn + n1) * Dc + kbase + bk0];

    for (int kb = 0; kb < NKB; kb++) {
        // store prefetched tile to smem
        As[(ak + 0) * AROW + am] = pa.x;
        As[(ak + 1) * AROW + am] = pa.y;
        As[(ak + 2) * AROW + am] = pa.z;
        As[(ak + 3) * AROW + am] = pa.w;
        Bs[(bk0 + 0) * BROW + n0] = pb0.x;
        Bs[(bk0 + 1) * BROW + n0] = pb0.y;
        Bs[(bk0 + 2) * BROW + n0] = pb0.z;
        Bs[(bk0 + 3) * BROW + n0] = pb0.w;
        Bs[(bk0 + 0) * BROW + n1] = pb1.x;
        Bs[(bk0 + 1) * BROW + n1] = pb1.y;
        Bs[(bk0 + 2) * BROW + n1] = pb1.z;
        Bs[(bk0 + 3) * BROW + n1] = pb1.w;
        __syncthreads();

        // prefetch next tile (hidden under compute)
        if (kb + 1 < NKB) {
            int k0 = kbase + (kb + 1) * BK;
            pa  = *(const float4*)&G[(bm + am) * Dc + k0 + ak];
            pb0 = *(const float4*)&W[(bn + n0) * Dc + k0 + bk0];
            pb1 = *(const float4*)&W[(bn + n1) * Dc + k0 + bk0];
        }

#pragma unroll
        for (int k = 0; k < BK; k++) {
            float4 a4 = *(const float4*)&As[k * AROW + tm];
            float4 b4 = *(const float4*)&Bs[k * BROW + tn];
            float a[4] = {a4.x, a4.y, a4.z, a4.w};
            float b[4] = {b4.x, b4.y, b4.z, b4.w};
#pragma unroll
            for (int i = 0; i < 4; i++)
#pragma unroll
                for (int j = 0; j < 4; j++)
                    cacc[i][j] = fmaf(a[i], b[j], cacc[i][j]);
        }
        __syncthreads();

        // Kahan fold every 2 BK blocks (chunk = 32 k values)
        if (kb & 1) {
#pragma unroll
            for (int i = 0; i < 4; i++)
#pragma unroll
                for (int j = 0; j < 4; j++) {
                    float y = __fsub_rn(cacc[i][j], kcmp[i][j]);
                    float t = __fadd_rn(ksum[i][j], y);
                    kcmp[i][j] = __fsub_rn(__fsub_rn(t, ksum[i][j]), y);
                    ksum[i][j] = t;
                    cacc[i][j] = 0.f;
                }
        }
    }

    // write corrected group partials to smem
#pragma unroll
    for (int i = 0; i < 4; i++)
#pragma unroll
        for (int j = 0; j < 4; j++)
            Ps[gid * (BM * BN) + (tm + i) * BN + (tn + j)] =
                __fsub_rn(ksum[i][j], kcmp[i][j]);
    __syncthreads();

    // merge groups (fixed order) + fused spike scan; 4 outputs per thread
    {
        const int idx = tid * 4;           // 0..2044, covers BM*BN = 2048
        const int m = idx >> 6;
        const int n = idx & 63;
        float4 v0 = *(const float4*)&Ps[0 * (BM * BN) + idx];
        float4 v1 = *(const float4*)&Ps[1 * (BM * BN) + idx];
        float4 v2 = *(const float4*)&Ps[2 * (BM * BN) + idx];
        float4 v3 = *(const float4*)&Ps[3 * (BM * BN) + idx];
        float av[4];
        av[0] = __fadd_rn(__fadd_rn(__fadd_rn(v0.x, v1.x), v2.x), v3.x);
        av[1] = __fadd_rn(__fadd_rn(__fadd_rn(v0.y, v1.y), v2.y), v3.y);
        av[2] = __fadd_rn(__fadd_rn(__fadd_rn(v0.z, v1.z), v2.z), v3.z);
        av[3] = __fadd_rn(__fadd_rn(__fadd_rn(v0.w, v1.w), v2.w), v3.w);

        const float thr = thresholds[l];
        float outv[4];
#pragma unroll
        for (int q = 0; q < 4; q++) {
            float a = av[q];
            int c;
            if (a <= 0.f) {
                c = 0;                      // thr > 0: m never exceeds thr
            } else if (a > thr) {
                c = Tc;                     // spikes every step, exactly
            } else {
                float mbr = 0.f;
                c = 0;
                for (int t = 0; t < Tc; t++) {
                    mbr += a;
                    if (mbr > thr) { mbr -= thr; c++; }
                }
            }
            outv[q] = (float)c * (1.0f / Tc);
        }
        *(float4*)&Rout[(bm + m) * Nc + bn + n] =
            make_float4(outv[0], outv[1], outv[2], outv[3]);
    }
}

// ---------------------------------------------------------------------------
__global__ void out_kernel(const float* __restrict__ R,
                           const int*   __restrict__ out_idx,
                           float*       __restrict__ out)
{
    int idx = blockIdx.x * blockDim.x + threadIdx.x;
    if (idx >= Bc * OUTc) return;
    int b = idx >> 10;
    int o = idx & 1023;
    out[idx] = R[(b << 11) + out_idx[o]] * (float)Tc;  // rate*64 = count, exact
}

// ---------------------------------------------------------------------------
extern "C" void kernel_launch(void* const* d_in, const int* in_sizes, int n_in,
                              void* d_out, int out_size)
{
    const float* x       = (const float*)d_in[0];   // [B, D]
    const float* W       = (const float*)d_in[1];   // [L, N, D]
    const float* thr     = (const float*)d_in[2];   // [L]
    const int*   axon    = (const int*)  d_in[3];   // [L, D]
    const int*   out_idx = (const int*)  d_in[4];   // [OUT]
    (void)in_sizes; (void)n_in; (void)out_size;

    cudaFuncSetAttribute(layer_kernel,
                         cudaFuncAttributeMaxDynamicSharedMemorySize,
                         SMEM_BYTES);

    float *G, *R0, *R1;
    cudaGetSymbolAddress((void**)&G,  g_G);
    cudaGetSymbolAddress((void**)&R0, g_R0);
    cudaGetSymbolAddress((void**)&R1, g_R1);
    float* bufs[2] = { R0, R1 };

    dim3 ggrid((Bc * Dc + 255) / 256);
    dim3 lgrid(Nc / BN, Bc / BM);   // (32, 4) = 128 blocks

    const float* rin = x;
    for (int l = 0; l < Lc; l++) {
        gather_kernel<<<ggrid, 256>>>(rin, axon + l * Dc, G);
        layer_kernel <<<lgrid, NTHREADS, SMEM_BYTES>>>(
            G, W + (size_t)l * Nc * Dc, thr, l, bufs[l & 1]);
        rin = bufs[l & 1];
    }
    out_kernel<<<(Bc * OUTc + 255) / 256, 256>>>(rin, out_idx, (float*)d_out);
}